// round 16
// baseline (speedup 1.0000x reference)
#include <cuda_runtime.h>

#define NTP 512   // threads per pass block; tiles are 2048 amps, 512 blocks

// State, tables, composed unitaries — __device__ globals (no allocs).
__device__ float2 g_psi[16 * 65536];
__device__ float2 g_U[240];        // 60 composed 2x2 unitaries
// Factored layer-0 ring-phase tables: phase(i) = lo[i&0x1FF] * hi[(i>>8)&0xFF | (i&1)<<8]
__device__ float2 g_f0lo[512], g_f0hi[512];   // depth 0
__device__ float2 g_f1lo[512], g_f1hi[512];   // depth 1
__device__ float2 g_t1[512];       // layer1 ring phases (2 depths x 256)
__device__ float2 g_t2[32];        // layer2 (2 x 16)
__device__ float2 g_t3[8];         // layer3 (2 x 4)

__device__ __forceinline__ float2 cmul(float2 a, float2 b) {
    return make_float2(fmaf(a.x, b.x, -a.y * b.y), fmaf(a.x, b.y, a.y * b.x));
}
__device__ __forceinline__ float2 cadd(float2 a, float2 b) {
    return make_float2(a.x + b.x, a.y + b.y);
}
__device__ __forceinline__ void mm2(const float2* A, const float2* B, float2* C) {
    C[0] = cadd(cmul(A[0], B[0]), cmul(A[1], B[2]));
    C[1] = cadd(cmul(A[0], B[1]), cmul(A[1], B[3]));
    C[2] = cadd(cmul(A[2], B[0]), cmul(A[3], B[2]));
    C[3] = cadd(cmul(A[2], B[1]), cmul(A[3], B[3]));
}

// Bank-conflict swizzle (involution); touches bits 0-3 only (stays in any
// 128-amp warp region).
__device__ __forceinline__ int SWZ(int i) { return i ^ ((i >> 4) & 15); }
__device__ __forceinline__ int insb(int x, int B) {
    return ((x >> B) << (B + 1)) | (x & ((1 << B) - 1));
}

// Layer-0 factored ring phase lookup (full 16-bit amp index, batch-free).
__device__ __forceinline__ float2 ring0_d0(int i) {
    return cmul(g_f0lo[i & 0x1FF], g_f0hi[((i >> 8) & 0xFF) | ((i & 1) << 8)]);
}
__device__ __forceinline__ float2 ring0_d1(int i) {
    return cmul(g_f1lo[i & 0x1FF], g_f1hi[((i >> 8) & 0xFF) | ((i & 1) << 8)]);
}

struct G4 { float2 a, b, c, d; };
__device__ __forceinline__ G4 ldG(int u) {
    return { g_U[4*u], g_U[4*u+1], g_U[4*u+2], g_U[4*u+3] };
}
__device__ __forceinline__ void gap(const G4& g, float2& x, float2& y) {
    float2 nx = cadd(cmul(g.a, x), cmul(g.b, y));
    float2 ny = cadd(cmul(g.c, x), cmul(g.d, y));
    x = nx; y = ny;
}

// ---------------------------------------------------------------------------
// Prep (tiny) — identical to R13.
// ---------------------------------------------------------------------------
__global__ __launch_bounds__(512) void prep_kernel(
    const float* __restrict__ p0, const float* __restrict__ p1,
    const float* __restrict__ p2, const float* __restrict__ p3,
    float* __restrict__ out)
{
    int T = blockIdx.x * 512 + threadIdx.x;

    if (T < 512) {
        float ph0 = 0.f, ph1 = 0.f;
        #pragma unroll
        for (int j = 7; j < 15; j++) {
            int x = ((T >> (15 - j)) ^ (T >> (14 - j))) & 1;
            float sg = x ? 0.5f : -0.5f;
            ph0 += sg * p0[4 * j + 3];
            ph1 += sg * p0[4 * j + 67];
        }
        g_f0lo[T] = make_float2(cosf(ph0), sinf(ph0));
        g_f1lo[T] = make_float2(cosf(ph1), sinf(ph1));
    } else if (T < 1024) {
        int ih = T - 512;
        float ph0 = 0.f, ph1 = 0.f;
        #pragma unroll
        for (int j = 0; j < 7; j++) {
            int x = ((ih >> (7 - j)) ^ (ih >> (6 - j))) & 1;
            float sg = x ? 0.5f : -0.5f;
            ph0 += sg * p0[4 * j + 3];
            ph1 += sg * p0[4 * j + 67];
        }
        {
            int x = ((ih >> 8) ^ (ih >> 7)) & 1;
            float sg = x ? 0.5f : -0.5f;
            ph0 += sg * p0[63];
            ph1 += sg * p0[127];
        }
        g_f0hi[ih] = make_float2(cosf(ph0), sinf(ph0));
        g_f1hi[ih] = make_float2(cosf(ph1), sinf(ph1));
    } else if (T < 1536) {
        int tt = T - 1024;
        int d = tt >> 8, idx = tt & 255;
        float ph = 0.f;
        #pragma unroll
        for (int j = 0; j < 8; j++) {
            int jn = (j + 1) & 7;
            int x = ((idx >> (7 - j)) ^ (idx >> (7 - jn))) & 1;
            ph += (x ? 0.5f : -0.5f) * p1[4 * j + 3 + 32 * d];
        }
        g_t1[tt] = make_float2(cosf(ph), sinf(ph));
    } else if (T < 1568) {
        int tt = T - 1536;
        int d = tt >> 4, idx = tt & 15;
        float ph = 0.f;
        #pragma unroll
        for (int j = 0; j < 4; j++) {
            int jn = (j + 1) & 3;
            int x = ((idx >> (3 - j)) ^ (idx >> (3 - jn))) & 1;
            ph += (x ? 0.5f : -0.5f) * p2[4 * j + 3 + 16 * d];
        }
        g_t2[tt] = make_float2(cosf(ph), sinf(ph));
    } else if (T < 1576) {
        int tt = T - 1568;
        int d = tt >> 2, idx = tt & 3;
        int x = ((idx >> 1) ^ idx) & 1;
        float sg = x ? 0.5f : -0.5f;
        float ph = sg * (p3[3 + 8 * d] + p3[7 + 8 * d]);
        g_t3[tt] = make_float2(cosf(ph), sinf(ph));
    } else if (T >= 1600 && T < 1660) {
        int t = T - 1600;
        const float* pp; int base;
        if (t < 32)      { pp = p0; int d = t >> 4;        int s = t & 15;       base = 4 * s + 64 * d; }
        else if (t < 48) { pp = p1; int d = (t - 32) >> 3; int s = (t - 32) & 7; base = 4 * s + 32 * d; }
        else if (t < 56) { pp = p2; int d = (t - 48) >> 2; int s = (t - 48) & 3; base = 4 * s + 16 * d; }
        else             { pp = p3; int d = (t - 56) >> 1; int s = (t - 56) & 1; base = 4 * s + 8 * d; }
        float a = pp[base] * 0.5f, b = pp[base + 1] * 0.5f, c = pp[base + 2] * 0.5f;
        float ca = cosf(a), sa = sinf(a);
        float cb = cosf(b), sb = sinf(b);
        float cc = cosf(c), sc = sinf(c);
        float2 RXa[4] = { {ca,0.f}, {0.f,-sa}, {0.f,-sa}, {ca,0.f} };
        float2 RZb[4] = { {cb,-sb}, {0.f,0.f}, {0.f,0.f}, {cb,sb} };
        float2 RXc[4] = { {cc,0.f}, {0.f,-sc}, {0.f,-sc}, {cc,0.f} };
        float2 M[4], U[4];
        mm2(RZb, RXa, M);
        mm2(RXc, M, U);
        g_U[t * 4 + 0] = U[0]; g_U[t * 4 + 1] = U[1];
        g_U[t * 4 + 2] = U[2]; g_U[t * 4 + 3] = U[3];
    } else if (T >= 1664 && T < 1680) {
        out[T - 1664] = 0.f;
    }
}

// ---------------------------------------------------------------------------
// Sweeps over a 2048-amp tile, 512 threads. sweep2: one 4-amp cell/thread.
// WL=true: bits < 7, cell inside the thread's warp 128-amp region.
// ---------------------------------------------------------------------------
template<int BH, int BL, bool WL, class LDF, class STF>
__device__ __forceinline__ void sweep2(int uh, int ul, LDF ld, STF st) {
    G4 H = ldG(uh), L = ldG(ul);
    int b0;
    if (WL) {
        int w = (int)threadIdx.x >> 5, l = (int)threadIdx.x & 31;
        b0 = (w << 7) | insb(insb(l, BL), BH);
    } else {
        b0 = insb(insb((int)threadIdx.x, BL), BH);
    }
    int j0 = b0 | (1 << BL), k0 = b0 | (1 << BH), m0 = k0 | (1 << BL);
    float2 a0 = ld(b0), a1 = ld(j0), a2 = ld(k0), a3 = ld(m0);
    gap(L, a0, a1); gap(L, a2, a3);
    gap(H, a0, a2); gap(H, a1, a3);
    st(b0, a0); st(j0, a1); st(k0, a2); st(m0, a3);
}

// Single-gate sweep: 1024 pairs, 2 per thread.
template<int B, bool WL, class LDF, class STF>
__device__ __forceinline__ void sweep1(int u, LDF ld, STF st) {
    G4 U = ldG(u);
    #pragma unroll
    for (int k = 0; k < 2; k++) {
        int i0;
        if (WL) {
            int w = (int)threadIdx.x >> 5, l = ((int)threadIdx.x & 31) + k * 32;
            i0 = (w << 7) | insb(l, B);
        } else {
            i0 = insb((int)threadIdx.x + k * NTP, B);
        }
        int i1 = i0 | (1 << B);
        float2 x = ld(i0), y = ld(i1);
        gap(U, x, y);
        st(i0, x); st(i1, y);
    }
}

// Combo: pre-gate upre on BH, elementwise diag ph, then uh on BH + ul on BL.
template<int BH, int BL, class PHF, class LDF, class STF>
__device__ __forceinline__ void sweep2c(int upre, int uh, int ul,
                                        PHF ph, LDF ld, STF st) {
    int b0 = insb(insb((int)threadIdx.x, BL), BH);
    int j0 = b0 | (1 << BL), k0 = b0 | (1 << BH), m0 = k0 | (1 << BL);
    float2 a0 = ld(b0), a1 = ld(j0), a2 = ld(k0), a3 = ld(m0);
    { G4 P = ldG(upre); gap(P, a0, a2); gap(P, a1, a3); }
    a0 = cmul(a0, ph(b0)); a1 = cmul(a1, ph(j0));
    a2 = cmul(a2, ph(k0)); a3 = cmul(a3, ph(m0));
    { G4 L = ldG(ul); gap(L, a0, a1); gap(L, a2, a3); }
    { G4 H = ldG(uh); gap(H, a0, a2); gap(H, a1, a3); }
    st(b0, a0); st(j0, a1); st(k0, a2); st(m0, a3);
}

// Measuring sweep: gates uh/ul with diag folded at load; Z-sign on bit BH.
template<int BH, int BL, class PHF, class LDF>
__device__ __forceinline__ float sweep2meas(int uh, int ul, PHF ph, LDF ld) {
    G4 H = ldG(uh), L = ldG(ul);
    int b0 = insb(insb((int)threadIdx.x, BL), BH);
    int j0 = b0 | (1 << BL), k0 = b0 | (1 << BH), m0 = k0 | (1 << BL);
    float2 a0 = cmul(ld(b0), ph(b0)), a1 = cmul(ld(j0), ph(j0));
    float2 a2 = cmul(ld(k0), ph(k0)), a3 = cmul(ld(m0), ph(m0));
    gap(L, a0, a1); gap(L, a2, a3);
    gap(H, a0, a2); gap(H, a1, a3);
    float acc = fmaf(a0.x, a0.x, a0.y * a0.y) + fmaf(a1.x, a1.x, a1.y * a1.y)
              - fmaf(a2.x, a2.x, a2.y * a2.y) - fmaf(a3.x, a3.x, a3.y * a3.y);
    return acc;
}

// Fused diagonal + CNOT-layer permutation (XOR involution), 4 amps/thread.
template<class FXF, class PHF>
__device__ __forceinline__ void perm_ph(float2* s, FXF fx, PHF ph) {
    #pragma unroll
    for (int i = 0; i < 4; i++) {
        int l = threadIdx.x + i * NTP;
        int f = fx(l);
        int p = l ^ f;
        if (f == 0) {
            s[SWZ(l)] = cmul(s[SWZ(l)], ph(l));
        } else if (l < p) {
            float2 a = s[SWZ(l)], b = s[SWZ(p)];
            s[SWZ(l)] = cmul(b, ph(p));
            s[SWZ(p)] = cmul(a, ph(l));
        }
    }
    __syncthreads();
}

// ---------------------------------------------------------------------------
// Pass A: globals = amp bits 15..11 (wires 0-4). Locals = bits 10..0 =
// wires 5..15; local bit b holds wire 15-b -> U(15-b). Layer0 d0 on w5..w15.
// ---------------------------------------------------------------------------
__global__ __launch_bounds__(NTP, 3) void passA_kernel(
    const float* __restrict__ xre, const float* __restrict__ xim)
{
    __shared__ float2 s[2048];
    int b = blockIdx.x >> 5, t = blockIdx.x & 31;
    int base = (b << 16) | (t << 11);
    auto SLD = [&](int l) { return s[SWZ(l)]; };
    auto SST = [&](int l, float2 v) { s[SWZ(l)] = v; };
    sweep2<10, 0, false>(5, 15,
        [&](int l) { return make_float2(xre[base + l], xim[base + l]); }, SST);
    __syncthreads();
    sweep2<9, 1, false>(6, 14, SLD, SST); __syncthreads();
    sweep2<8, 2, false>(7, 13, SLD, SST); __syncthreads();
    sweep2<7, 3, false>(8, 12, SLD, SST); __syncthreads();
    sweep2<6, 4, true>(9, 11, SLD, SST);  __syncwarp();
    sweep1<5, true>(10, SLD,
        [&](int l, float2 v) { g_psi[base + l] = v; });
}

// ---------------------------------------------------------------------------
// Pass B: globals = amp bits 10..6 (wires 5-9), tor = t<<6.
// Locals l10..l6 = amp bits 15..11 (wires 0-4); l5..l0 = amp bits 5..0
// (wires 10-15). expandB(l) = (l&0x3F) | ((l&0x7C0)<<5).
// Work: d0 U0..U4; ring-d0 diag; d1 U16..U20 (w0-4) + U26..U31 (w10-15).
// ---------------------------------------------------------------------------
__device__ __forceinline__ int expandB(int l) {
    return (l & 0x3F) | ((l & 0x7C0) << 5);
}
__global__ __launch_bounds__(NTP, 3) void passB_kernel() {
    __shared__ float2 s[2048];
    int b = blockIdx.x >> 5, t = blockIdx.x & 31;
    unsigned tor = (unsigned)t << 6;
    unsigned gb = (unsigned)b << 16;
    auto SLD = [&](int l) { return s[SWZ(l)]; };
    auto SST = [&](int l, float2 v) { s[SWZ(l)] = v; };
    sweep2<10, 9, false>(0, 1,
        [&](int l) { return g_psi[gb | tor | expandB(l)]; }, SST);
    __syncthreads();
    sweep2<8, 7, false>(2, 3, SLD, SST); __syncthreads();
    // U4 (d0 on l6) -> ring-d0 diag -> d1 U20@l6, U26@l5
    sweep2c<6, 5>(4, 20, 26,
        [&](int l) { return ring0_d0(tor | expandB(l)); }, SLD, SST);
    __syncthreads();
    sweep2<10, 0, false>(16, 31, SLD, SST); __syncthreads();
    sweep2<9, 1, false>(17, 30, SLD, SST);  __syncthreads();
    sweep2<8, 2, false>(18, 29, SLD, SST);  __syncthreads();
    sweep2<7, 3, false>(19, 28, SLD, SST);  __syncthreads();
    sweep1<4, true>(27, SLD,
        [&](int l, float2 v) { g_psi[gb | tor | expandB(l)] = v; });
}

// ---------------------------------------------------------------------------
// Pass C: globals = wires 0,2,4,10,12 -> amp bits 15,13,11,5,3.
// tor: t0->b3, t1->b5, t2->b11, t3->b13, t4->b15.
// Locals: l10=b14(w1) l9=b12(w3) l8=b10(w5) l7=b9(w6) l6=b8(w7) l5=b7(w8)
//         l4=b6(w9) l3=b4(w11) l2=b2(w13) l1=b1(w14) l0=b0(w15).
// Work: d1 U21@l8,U22@l7,U23@l6,U24@l5,U25@l4; ring-d1 + pool0 perm;
//       layer1 d0: U35@l7(w6), U36@l5(w8), U39@l1(w14).
// ---------------------------------------------------------------------------
__device__ __forceinline__ int expandC(int l) {
    return (l & 7) | ((l & 8) << 1) | ((l & 0x1F0) << 2) |
           ((l & 0x200) << 3) | ((l & 0x400) << 4);
}
__global__ __launch_bounds__(NTP, 3) void passC_kernel() {
    __shared__ float2 s[2048];
    int b = blockIdx.x >> 5, t = blockIdx.x & 31;
    unsigned tor = ((t & 1) << 3) | ((t & 2) << 4) | ((t & 4) << 9) |
                   ((t & 8) << 10) | ((t & 16) << 11);
    unsigned gb = (unsigned)b << 16;
    auto SLD = [&](int l) { return s[SWZ(l)]; };
    auto SST = [&](int l, float2 v) { s[SWZ(l)] = v; };
    sweep2<8, 7, false>(21, 22,
        [&](int l) { return g_psi[gb | tor | expandC(l)]; }, SST);
    __syncthreads();
    sweep2<6, 5, true>(23, 24, SLD, SST); __syncwarp();
    sweep1<4, true>(25, SLD, SST);        __syncthreads();
    // ring-d1 + pool0: flip l6 if l7; l4 if l5; l0 if l1; l10/l9/l8/l3/l2 by
    // global controls w0(t4), w2(t3), w4(t2), w10(t1), w12(t0).
    {
        int fc = ((t >> 4) & 1) << 10 | ((t >> 3) & 1) << 9 | ((t >> 2) & 1) << 8 |
                 ((t >> 1) & 1) << 3 | (t & 1) << 2;
        perm_ph(s,
            [&](int l) {
                return ((((l >> 7) & 1) << 6) | (((l >> 5) & 1) << 4) |
                        ((l >> 1) & 1)) | fc;
            },
            [&](int l) { return ring0_d1(tor | expandC(l)); });
    }
    sweep2<7, 5, false>(35, 36, SLD, SST); __syncthreads();
    sweep1<1, true>(39, SLD,
        [&](int l, float2 v) { g_psi[gb | tor | expandC(l)] = v; });
}

// ---------------------------------------------------------------------------
// Pass D: globals = wires 1,3,5,7,9 -> amp bits 14,12,10,8,6.
// tor: t0->b6, t1->b8, t2->b10, t3->b12, t4->b14.
// Locals: l10=b15(w0) l9=b13(w2) l8=b11(w4) l7=b9(w6) l6=b7(w8) l5=b5(w10)
//         l4=b4(w11) l3=b3(w12) l2=b2(w13) l1=b1(w14) l0=b0(w15).
// Work: layer1 d0 U32@l10,U33@l9,U34@l8,U37@l5,U38@l3; ring1-d0 diag;
//   layer1 d1 U40..U47; ring1-d1+pool1 perm; layer2 (U48-55, diags, pool2);
//   layer3 U56-59 + t3-d0 diag + measure Z on l10 (t3-d1+pool3 are no-ops).
// ---------------------------------------------------------------------------
__device__ __forceinline__ int expandD(int l) {
    return (l & 0x3F) | ((l & 0x40) << 1) | ((l & 0x80) << 2) |
           ((l & 0x100) << 3) | ((l & 0x200) << 4) | ((l & 0x400) << 5);
}
__device__ __forceinline__ int pD_idx8(int l) {
    return ((l >> 3) & 0xFC) | ((l >> 2) & 2) | ((l >> 1) & 1);
}
__device__ __forceinline__ int pD_idx4(int l) {
    return (((l >> 10) & 1) << 3) | (((l >> 8) & 1) << 2) |
           (((l >> 6) & 1) << 1) | ((l >> 3) & 1);
}
__device__ __forceinline__ int pD_idx2(int l) {
    return (((l >> 10) & 1) << 1) | ((l >> 6) & 1);
}
__global__ __launch_bounds__(NTP, 3) void passD_kernel(float* __restrict__ out) {
    __shared__ float2 s[2048];
    __shared__ float ws[16];
    int tid = threadIdx.x;
    int b = blockIdx.x >> 5, t = blockIdx.x & 31;
    unsigned tor = ((t & 1) << 6) | ((t & 2) << 7) | ((t & 4) << 8) |
                   ((t & 8) << 9) | ((t & 16) << 10);
    unsigned gb = (unsigned)b << 16;
    auto SLD = [&](int l) { return s[SWZ(l)]; };
    auto SST = [&](int l, float2 v) { s[SWZ(l)] = v; };

    // layer1 d0 leftovers
    sweep2<10, 9, false>(32, 33,
        [&](int l) { return g_psi[gb | tor | expandD(l)]; }, SST);
    __syncthreads();
    sweep2<8, 5, false>(34, 37, SLD, SST); __syncthreads();
    // U38 (d0 on l3) -> ring1-d0 diag -> d1 U46@l3, U47@l1
    sweep2c<3, 1>(38, 46, 47,
        [&](int l) { return g_t1[pD_idx8(l)]; }, SLD, SST);
    __syncthreads();
    // layer1 d1 rest
    sweep2<10, 9, false>(40, 41, SLD, SST); __syncthreads();
    sweep2<8, 7, false>(42, 43, SLD, SST);  __syncthreads();
    sweep2<6, 5, true>(44, 45, SLD, SST);   __syncthreads();
    // ring1-d1 + pool1 (flip l9 if l10; l7 if l8; l5 if l6; l1 if l3)
    perm_ph(s,
        [&](int l) {
            return (((l >> 10) & 1) << 9) | (((l >> 8) & 1) << 7) |
                   (((l >> 6) & 1) << 5) | (((l >> 3) & 1) << 1);
        },
        [&](int l) { return g_t1[256 + pD_idx8(l)]; });

    // layer2 d0: U48@l10, U49@l8, U50@l6, U51@l3
    sweep2<10, 8, false>(48, 49, SLD, SST); __syncthreads();
    sweep2<6, 3, true>(50, 51, SLD, SST);   __syncthreads();
    // layer2 d1 with ring2-d0 diag folded
    sweep2<10, 8, false>(52, 53,
        [&](int l) { return cmul(s[SWZ(l)], g_t2[pD_idx4(l)]); }, SST);
    __syncthreads();
    sweep2<6, 3, true>(54, 55, SLD, SST); __syncthreads();
    // ring2-d1 + pool2 (flip l8 if l10; l3 if l6)
    perm_ph(s,
        [&](int l) {
            return (((l >> 10) & 1) << 8) | (((l >> 6) & 1) << 3);
        },
        [&](int l) { return g_t2[16 + pD_idx4(l)]; });

    // layer3 d0: U56@l10, U57@l6
    sweep2<10, 6, false>(56, 57, SLD, SST); __syncthreads();
    // layer3 d1 (U58@l10, U59@l6) with t3-d0 diag folded + measure Z(l10)
    float acc = sweep2meas<10, 6>(58, 59,
        [&](int l) { return g_t3[pD_idx2(l)]; }, SLD);

    #pragma unroll
    for (int o = 16; o > 0; o >>= 1) acc += __shfl_xor_sync(0xFFFFFFFFu, acc, o);
    if ((tid & 31) == 0) ws[tid >> 5] = acc;
    __syncthreads();
    if (tid == 0) {
        float tt = 0.f;
        #pragma unroll
        for (int k = 0; k < 16; k++) tt += ws[k];
        atomicAdd(&out[b], tt);
    }
}

// ---------------------------------------------------------------------------
extern "C" void kernel_launch(void* const* d_in, const int* in_sizes, int n_in,
                              void* d_out, int out_size) {
    const float* xre = (const float*)d_in[0];
    const float* xim = (const float*)d_in[1];
    const float* p0  = (const float*)d_in[2];
    const float* p1  = (const float*)d_in[3];
    const float* p2  = (const float*)d_in[4];
    const float* p3  = (const float*)d_in[5];
    float* out = (float*)d_out;

    prep_kernel<<<8, 512>>>(p0, p1, p2, p3, out);
    passA_kernel<<<512, NTP>>>(xre, xim);
    passB_kernel<<<512, NTP>>>();
    passC_kernel<<<512, NTP>>>();
    passD_kernel<<<512, NTP>>>(out);
}

// round 17
// speedup vs baseline: 1.1701x; 1.1701x over previous
#include <cuda_runtime.h>

#define NTP 512   // pass threads

// 8 MB state, tables, composed unitaries — all __device__ globals (no allocs).
__device__ float2 g_psi[16 * 65536];
__device__ float2 g_U[240];        // 60 composed 2x2 unitaries
// Factored layer-0 ring-phase tables: phase(i) = lo[i&0x1FF] * hi[(i>>8)&0xFF | (i&1)<<8]
__device__ float2 g_f0lo[512], g_f0hi[512];   // depth 0
__device__ float2 g_f1lo[512], g_f1hi[512];   // depth 1
__device__ float2 g_t1[512];       // layer1 ring phases (2 depths x 256)
__device__ float2 g_t2[32];        // layer2 (2 x 16)
__device__ float2 g_t3[8];         // layer3 (2 x 4)

__device__ __forceinline__ float2 cmul(float2 a, float2 b) {
    return make_float2(fmaf(a.x, b.x, -a.y * b.y), fmaf(a.x, b.y, a.y * b.x));
}
__device__ __forceinline__ float2 cadd(float2 a, float2 b) {
    return make_float2(a.x + b.x, a.y + b.y);
}
__device__ __forceinline__ void mm2(const float2* A, const float2* B, float2* C) {
    C[0] = cadd(cmul(A[0], B[0]), cmul(A[1], B[2]));
    C[1] = cadd(cmul(A[0], B[1]), cmul(A[1], B[3]));
    C[2] = cadd(cmul(A[2], B[0]), cmul(A[3], B[2]));
    C[3] = cadd(cmul(A[2], B[1]), cmul(A[3], B[3]));
}

// Bank-conflict swizzle (involution, GF(2)-linear): XOR low nibble with bits 4-7.
__device__ __forceinline__ int SWZ(int i) { return i ^ ((i >> 4) & 15); }
// Compile-time swizzle of a single bit (for constant XOR deltas).
__host__ __device__ constexpr int SWC(int B) {
    return (1 << B) ^ (((1 << B) >> 4) & 15);
}
// Insert a zero bit at position B.
__device__ __forceinline__ int insb(int x, int B) {
    return ((x >> B) << (B + 1)) | (x & ((1 << B) - 1));
}

// Layer-0 factored ring phase lookup (full 16-bit amp index, batch-free).
__device__ __forceinline__ float2 ring0_d0(int i) {
    return cmul(g_f0lo[i & 0x1FF], g_f0hi[((i >> 8) & 0xFF) | ((i & 1) << 8)]);
}
__device__ __forceinline__ float2 ring0_d1(int i) {
    return cmul(g_f1lo[i & 0x1FF], g_f1hi[((i >> 8) & 0xFF) | ((i & 1) << 8)]);
}

// 2x2 gate coefficients + FUSED pair application: each output component is a
// 4-op FMUL+FFMA chain (16 ops/pair vs 20 for cmul/cadd composition).
struct G4 { float2 a, b, c, d; };
__device__ __forceinline__ G4 ldG(int u) {
    return { g_U[4*u], g_U[4*u+1], g_U[4*u+2], g_U[4*u+3] };
}
__device__ __forceinline__ void gap(const G4& g, float2& x, float2& y) {
    float xr = x.x, xi = x.y, yr = y.x, yi = y.y;
    float nxr = fmaf(g.b.x, yr, g.a.x * xr);
    nxr = fmaf(-g.a.y, xi, nxr);
    nxr = fmaf(-g.b.y, yi, nxr);
    float nxi = fmaf(g.b.x, yi, g.a.x * xi);
    nxi = fmaf(g.a.y, xr, nxi);
    nxi = fmaf(g.b.y, yr, nxi);
    float nyr = fmaf(g.d.x, yr, g.c.x * xr);
    nyr = fmaf(-g.c.y, xi, nyr);
    nyr = fmaf(-g.d.y, yi, nyr);
    float nyi = fmaf(g.d.x, yi, g.c.x * xi);
    nyi = fmaf(g.c.y, xr, nyi);
    nyi = fmaf(g.d.y, yr, nyi);
    x = make_float2(nxr, nxi);
    y = make_float2(nyr, nyi);
}

// ---------------------------------------------------------------------------
// Prep (tiny) — unchanged from R13.
// ---------------------------------------------------------------------------
__global__ __launch_bounds__(512) void prep_kernel(
    const float* __restrict__ p0, const float* __restrict__ p1,
    const float* __restrict__ p2, const float* __restrict__ p3,
    float* __restrict__ out)
{
    int T = blockIdx.x * 512 + threadIdx.x;

    if (T < 512) {
        float ph0 = 0.f, ph1 = 0.f;
        #pragma unroll
        for (int j = 7; j < 15; j++) {
            int x = ((T >> (15 - j)) ^ (T >> (14 - j))) & 1;
            float sg = x ? 0.5f : -0.5f;
            ph0 += sg * p0[4 * j + 3];
            ph1 += sg * p0[4 * j + 67];
        }
        g_f0lo[T] = make_float2(cosf(ph0), sinf(ph0));
        g_f1lo[T] = make_float2(cosf(ph1), sinf(ph1));
    } else if (T < 1024) {
        int ih = T - 512;
        float ph0 = 0.f, ph1 = 0.f;
        #pragma unroll
        for (int j = 0; j < 7; j++) {
            int x = ((ih >> (7 - j)) ^ (ih >> (6 - j))) & 1;
            float sg = x ? 0.5f : -0.5f;
            ph0 += sg * p0[4 * j + 3];
            ph1 += sg * p0[4 * j + 67];
        }
        {
            int x = ((ih >> 8) ^ (ih >> 7)) & 1;
            float sg = x ? 0.5f : -0.5f;
            ph0 += sg * p0[63];
            ph1 += sg * p0[127];
        }
        g_f0hi[ih] = make_float2(cosf(ph0), sinf(ph0));
        g_f1hi[ih] = make_float2(cosf(ph1), sinf(ph1));
    } else if (T < 1536) {
        int tt = T - 1024;
        int d = tt >> 8, idx = tt & 255;
        float ph = 0.f;
        #pragma unroll
        for (int j = 0; j < 8; j++) {
            int jn = (j + 1) & 7;
            int x = ((idx >> (7 - j)) ^ (idx >> (7 - jn))) & 1;
            ph += (x ? 0.5f : -0.5f) * p1[4 * j + 3 + 32 * d];
        }
        g_t1[tt] = make_float2(cosf(ph), sinf(ph));
    } else if (T < 1568) {
        int tt = T - 1536;
        int d = tt >> 4, idx = tt & 15;
        float ph = 0.f;
        #pragma unroll
        for (int j = 0; j < 4; j++) {
            int jn = (j + 1) & 3;
            int x = ((idx >> (3 - j)) ^ (idx >> (3 - jn))) & 1;
            ph += (x ? 0.5f : -0.5f) * p2[4 * j + 3 + 16 * d];
        }
        g_t2[tt] = make_float2(cosf(ph), sinf(ph));
    } else if (T < 1576) {
        int tt = T - 1568;
        int d = tt >> 2, idx = tt & 3;
        int x = ((idx >> 1) ^ idx) & 1;
        float sg = x ? 0.5f : -0.5f;
        float ph = sg * (p3[3 + 8 * d] + p3[7 + 8 * d]);
        g_t3[tt] = make_float2(cosf(ph), sinf(ph));
    } else if (T >= 1600 && T < 1660) {
        int t = T - 1600;
        const float* pp; int base;
        if (t < 32)      { pp = p0; int d = t >> 4;        int s = t & 15;       base = 4 * s + 64 * d; }
        else if (t < 48) { pp = p1; int d = (t - 32) >> 3; int s = (t - 32) & 7; base = 4 * s + 32 * d; }
        else if (t < 56) { pp = p2; int d = (t - 48) >> 2; int s = (t - 48) & 3; base = 4 * s + 16 * d; }
        else             { pp = p3; int d = (t - 56) >> 1; int s = (t - 56) & 1; base = 4 * s + 8 * d; }
        float a = pp[base] * 0.5f, b = pp[base + 1] * 0.5f, c = pp[base + 2] * 0.5f;
        float ca = cosf(a), sa = sinf(a);
        float cb = cosf(b), sb = sinf(b);
        float cc = cosf(c), sc = sinf(c);
        float2 RXa[4] = { {ca,0.f}, {0.f,-sa}, {0.f,-sa}, {ca,0.f} };
        float2 RZb[4] = { {cb,-sb}, {0.f,0.f}, {0.f,0.f}, {cb,sb} };
        float2 RXc[4] = { {cc,0.f}, {0.f,-sc}, {0.f,-sc}, {cc,0.f} };
        float2 M[4], U[4];
        mm2(RZb, RXa, M);
        mm2(RXc, M, U);
        g_U[t * 4 + 0] = U[0]; g_U[t * 4 + 1] = U[1];
        g_U[t * 4 + 2] = U[2]; g_U[t * 4 + 3] = U[3];
    } else if (T >= 1664 && T < 1680) {
        out[T - 1664] = 0.f;
    }
}

// ---------------------------------------------------------------------------
// Smem-direct 2-gate sweep: ONE swizzle per cell base, neighbors by constant
// XOR deltas (SWZ is linear; cell bits are zero in the base so OR == XOR).
// Two cells per thread, all 8 loads batched (MLP=8).
// WL=true: BH,BL < 8, cells inside the thread's warp 256-amp region.
// ---------------------------------------------------------------------------
template<int BH, int BL, bool WL>
__device__ __forceinline__ void sweep2s(float2* s, int uh, int ul) {
    G4 H = ldG(uh), L = ldG(ul);
    constexpr int DL = SWC(BL), DH = SWC(BH);
    int b0, b1;
    if (WL) {
        int w = (int)threadIdx.x >> 5, l = (int)threadIdx.x & 31;
        b0 = (w << 8) | insb(insb(l, BL), BH);
        b1 = (w << 8) | insb(insb(l + 32, BL), BH);
    } else {
        b0 = insb(insb((int)threadIdx.x, BL), BH);
        b1 = insb(insb((int)threadIdx.x + NTP, BL), BH);
    }
    int s0 = SWZ(b0), s1 = SWZ(b1);
    float2 a0 = s[s0], a1 = s[s0 ^ DL], a2 = s[s0 ^ DH], a3 = s[s0 ^ DH ^ DL];
    float2 c0 = s[s1], c1 = s[s1 ^ DL], c2 = s[s1 ^ DH], c3 = s[s1 ^ DH ^ DL];
    gap(L, a0, a1); gap(L, a2, a3); gap(H, a0, a2); gap(H, a1, a3);
    s[s0] = a0; s[s0 ^ DL] = a1; s[s0 ^ DH] = a2; s[s0 ^ DH ^ DL] = a3;
    gap(L, c0, c1); gap(L, c2, c3); gap(H, c0, c2); gap(H, c1, c3);
    s[s1] = c0; s[s1 ^ DL] = c1; s[s1 ^ DH] = c2; s[s1 ^ DH ^ DL] = c3;
}

// Same, with an elementwise phase applied at load (phase takes LOGICAL index).
template<int BH, int BL, bool WL, class PHF>
__device__ __forceinline__ void sweep2sp(float2* s, int uh, int ul, PHF ph) {
    G4 H = ldG(uh), L = ldG(ul);
    constexpr int DL = SWC(BL), DH = SWC(BH);
    int b0, b1;
    if (WL) {
        int w = (int)threadIdx.x >> 5, l = (int)threadIdx.x & 31;
        b0 = (w << 8) | insb(insb(l, BL), BH);
        b1 = (w << 8) | insb(insb(l + 32, BL), BH);
    } else {
        b0 = insb(insb((int)threadIdx.x, BL), BH);
        b1 = insb(insb((int)threadIdx.x + NTP, BL), BH);
    }
    int s0 = SWZ(b0), s1 = SWZ(b1);
    float2 a0 = cmul(s[s0],           ph(b0));
    float2 a1 = cmul(s[s0 ^ DL],      ph(b0 | (1 << BL)));
    float2 a2 = cmul(s[s0 ^ DH],      ph(b0 | (1 << BH)));
    float2 a3 = cmul(s[s0 ^ DH ^ DL], ph(b0 | (1 << BH) | (1 << BL)));
    float2 c0 = cmul(s[s1],           ph(b1));
    float2 c1 = cmul(s[s1 ^ DL],      ph(b1 | (1 << BL)));
    float2 c2 = cmul(s[s1 ^ DH],      ph(b1 | (1 << BH)));
    float2 c3 = cmul(s[s1 ^ DH ^ DL], ph(b1 | (1 << BH) | (1 << BL)));
    gap(L, a0, a1); gap(L, a2, a3); gap(H, a0, a2); gap(H, a1, a3);
    s[s0] = a0; s[s0 ^ DL] = a1; s[s0 ^ DH] = a2; s[s0 ^ DH ^ DL] = a3;
    gap(L, c0, c1); gap(L, c2, c3); gap(H, c0, c2); gap(H, c1, c3);
    s[s1] = c0; s[s1 ^ DL] = c1; s[s1 ^ DH] = c2; s[s1 ^ DH ^ DL] = c3;
}

// Generic lambda sweep (for fused global load/store ends). MLP=8.
template<int BH, int BL, bool WL, class LDF, class STF>
__device__ __forceinline__ void sweep2(int uh, int ul, LDF ld, STF st) {
    G4 H = ldG(uh), L = ldG(ul);
    int b0, b1;
    if (WL) {
        int w = (int)threadIdx.x >> 5, l = (int)threadIdx.x & 31;
        b0 = (w << 8) | insb(insb(l, BL), BH);
        b1 = (w << 8) | insb(insb(l + 32, BL), BH);
    } else {
        b0 = insb(insb((int)threadIdx.x, BL), BH);
        b1 = insb(insb((int)threadIdx.x + NTP, BL), BH);
    }
    int j0 = b0 | (1 << BL), k0 = b0 | (1 << BH), m0 = k0 | (1 << BL);
    int j1 = b1 | (1 << BL), k1 = b1 | (1 << BH), m1 = k1 | (1 << BL);
    float2 a0 = ld(b0), a1 = ld(j0), a2 = ld(k0), a3 = ld(m0);
    float2 c0 = ld(b1), c1 = ld(j1), c2 = ld(k1), c3 = ld(m1);
    gap(L, a0, a1); gap(L, a2, a3); gap(H, a0, a2); gap(H, a1, a3);
    st(b0, a0); st(j0, a1); st(k0, a2); st(m0, a3);
    gap(L, c0, c1); gap(L, c2, c3); gap(H, c0, c2); gap(H, c1, c3);
    st(b1, c0); st(j1, c1); st(k1, c2); st(m1, c3);
}

// ---------------------------------------------------------------------------
// Fused diagonal + CNOT-layer permutation (XOR involution). new[l]=old[p]*ph(p).
// ---------------------------------------------------------------------------
template<class FXF, class PHF>
__device__ __forceinline__ void perm_ph(float2* s, FXF fx, PHF ph) {
    #pragma unroll
    for (int i = 0; i < 8; i++) {
        int l = threadIdx.x + i * NTP;
        int f = fx(l);
        int p = l ^ f;
        if (f == 0) {
            s[SWZ(l)] = cmul(s[SWZ(l)], ph(l));
        } else if (l < p) {
            float2 a = s[SWZ(l)], b = s[SWZ(p)];
            s[SWZ(l)] = cmul(b, ph(p));
            s[SWZ(p)] = cmul(a, ph(l));
        }
    }
    __syncthreads();
}

// ---------------------------------------------------------------------------
// Pass 1: local = amp bits 0..11 (wires 4..15). Layer0 d0 on wires 4..15.
// Local bit b holds wire 15-b -> U(15-b).
// ---------------------------------------------------------------------------
__global__ __launch_bounds__(NTP, 2) void pass1_kernel(
    const float* __restrict__ xre, const float* __restrict__ xim)
{
    __shared__ float2 s[4096];
    int b = blockIdx.x >> 4, tile = blockIdx.x & 15;
    int base = (b << 16) | (tile << 12);
    auto SST = [&](int l, float2 v) { s[SWZ(l)] = v; };
    sweep2<7, 0, true>(8, 15,
        [&](int l) { return make_float2(xre[base + l], xim[base + l]); }, SST);
    __syncwarp();
    sweep2s<6, 1, true>(s, 9, 14);  __syncwarp();
    sweep2s<5, 2, true>(s, 10, 13); __syncwarp();
    sweep2s<4, 3, true>(s, 11, 12); __syncthreads();
    sweep2s<11, 8, false>(s, 4, 7); __syncthreads();
    sweep2<10, 9, false>(5, 6,
        [&](int l) { return s[SWZ(l)]; },
        [&](int l, float2 v) { g_psi[base + l] = v; });
}

// ---------------------------------------------------------------------------
// Pass 2: local amp bits {0-4,7,9,11,12-15}. d0 on wires 0-3; ring D0; d1 on
// 12 local wires. Global amp bits {5,6,8,10}.
// ---------------------------------------------------------------------------
__device__ __forceinline__ int expand2x(int l) {
    return (l & 0x1F) | ((l & 0x20) << 2) | ((l & 0x40) << 3) | ((l & 0xF80) << 4);
}
__global__ __launch_bounds__(NTP, 2) void pass2_kernel() {
    __shared__ float2 s[4096];
    int b = blockIdx.x >> 4, tile = blockIdx.x & 15;
    unsigned tor = ((tile & 3) << 5) | ((tile & 4) << 6) | ((tile & 8) << 7);
    unsigned gb = (unsigned)b << 16;
    auto SST = [&](int l, float2 v) { s[SWZ(l)] = v; };
    sweep2<11, 8, false>(0, 3,
        [&](int l) { return g_psi[gb | tor | expand2x(l)]; }, SST);
    __syncthreads();
    sweep2s<10, 9, false>(s, 1, 2); __syncthreads();
    // layer0 d1; ring diag D0 folded into the first d1 sweep's load
    sweep2sp<7, 0, true>(s, 20, 31,
        [&](int l) { return ring0_d0(tor | expand2x(l)); });
    __syncwarp();
    sweep2s<6, 1, true>(s, 22, 30);   __syncwarp();
    sweep2s<5, 2, true>(s, 24, 29);   __syncwarp();
    sweep2s<4, 3, true>(s, 27, 28);   __syncthreads();
    sweep2s<11, 8, false>(s, 16, 19); __syncthreads();
    sweep2<10, 9, false>(17, 18,
        [&](int l) { return s[SWZ(l)]; },
        [&](int l, float2 v) { g_psi[gb | tor | expand2x(l)] = v; });
}

// ---------------------------------------------------------------------------
// Pass 3: local amp bits {0-6,8,10,12,14,15}. Global amp bits {7,9,11,13}.
// Local map: l11=w0 l10=w1 l9=w3 l8=w5 l7=w7 l6=w9 l5=w10 l4..l0=w11..w15.
// ---------------------------------------------------------------------------
__device__ __forceinline__ int expand3x(int l) {
    return (l & 0x7F) | ((l & 0x80) << 1) | ((l & 0x100) << 2) |
           ((l & 0x200) << 3) | ((l & 0xC00) << 4);
}
__global__ __launch_bounds__(NTP, 2) void pass3_kernel() {
    __shared__ float2 s[4096];
    int b = blockIdx.x >> 4, tile = blockIdx.x & 15;
    unsigned tor = ((tile & 1) << 7) | ((tile & 2) << 8) | ((tile & 4) << 9) | ((tile & 8) << 10);
    unsigned gb = (unsigned)b << 16;
    auto SST = [&](int l, float2 v) { s[SWZ(l)] = v; };
    // layer0 d1 leftovers: w5->l8(U21), w7->l7(U23), w9->l6(U25), w10->l5(U26)
    sweep2<8, 5, false>(21, 26,
        [&](int l) { return g_psi[gb | tor | expand3x(l)]; }, SST);
    __syncthreads();
    sweep2s<7, 6, true>(s, 23, 25); __syncthreads();
    // ring D1 + all 8 pool CNOTs fused (targets l10,l9,l8,l7,l6,l4,l2,l0).
    {
        int fc = (((tile >> 3) & 1) << 9) | (((tile >> 2) & 1) << 8) |
                 (((tile >> 1) & 1) << 7) | ((tile & 1) << 6);
        perm_ph(s,
            [&](int l) {
                return ((((l >> 11) & 1) << 10) | (((l >> 5) & 1) << 4) |
                        (((l >> 3) & 1) << 2) | ((l >> 1) & 1)) | fc;
            },
            [&](int l) { return ring0_d1(tor | expand3x(l)); });
    }
    // layer1 d0 on wires 0,10,12,14 -> locals 11(U32),5(U37),3(U38),1(U39)
    sweep2s<11, 1, false>(s, 32, 39); __syncthreads();
    sweep2<5, 3, true>(37, 38,
        [&](int l) { return s[SWZ(l)]; },
        [&](int l, float2 v) { g_psi[gb | tor | expand3x(l)] = v; });
}

// ---------------------------------------------------------------------------
// Pass 4: local amp bits {0-7,9,11,13,15}. Global amp bits {8,10,12,14}.
// Local map: l11=w0 l10=w2 l9=w4 l8=w6 l7=w8 l5=w10 l3=w12 l1=w14.
// Final diagonal (t3 d1) and final pool CNOT (ctrl=bit11, tgt=bit7) cannot
// change <Z(bit11)> — dropped. Measurement fused into the last unitary sweep.
// ---------------------------------------------------------------------------
__device__ __forceinline__ int expand4x(int l) {
    return (l & 0xFF) | ((l & 0x100) << 1) | ((l & 0x200) << 2) |
           ((l & 0x400) << 3) | ((l & 0x800) << 4);
}
__device__ __forceinline__ int p4_idx8(int l) {
    return ((l >> 4) & 0xF8) | ((l >> 3) & 4) | ((l >> 2) & 2) | ((l >> 1) & 1);
}
__device__ __forceinline__ int p4_idx4(int l) {
    return ((l >> 8) & 8) | ((l >> 7) & 4) | ((l >> 6) & 2) | ((l >> 3) & 1);
}
__device__ __forceinline__ int p4_idx2(int l) {
    return ((l >> 10) & 2) | ((l >> 7) & 1);
}
__global__ __launch_bounds__(NTP, 2) void pass4_kernel(float* __restrict__ out) {
    __shared__ float2 s[4096];
    __shared__ float ws[16];
    int tid = threadIdx.x;
    int b = blockIdx.x >> 4, tile = blockIdx.x & 15;
    unsigned tor = ((tile & 1) << 8) | ((tile & 2) << 9) | ((tile & 4) << 10) | ((tile & 8) << 11);
    unsigned gb = (unsigned)b << 16;
    auto SST = [&](int l, float2 v) { s[SWZ(l)] = v; };

    // layer1 d0 leftovers: w2->l10(U33), w4->l9(U34), w6->l8(U35), w8->l7(U36)
    sweep2<10, 9, false>(33, 34,
        [&](int l) { return g_psi[gb | tor | expand4x(l)]; }, SST);
    __syncthreads();
    sweep2s<8, 7, false>(s, 35, 36); __syncthreads();
    // layer1 d1 (8 gates) with ring d0 folded into the first sweep
    sweep2sp<11, 8, false>(s, 40, 43,
        [&](int l) { return g_t1[p4_idx8(l)]; });
    __syncthreads();
    sweep2s<10, 9, false>(s, 41, 42); __syncthreads();
    sweep2s<7, 5, true>(s, 44, 45);   __syncwarp();
    sweep2s<3, 1, true>(s, 46, 47);   __syncthreads();
    // ring d1 + layer1 pool (l10<-l11, l8<-l9, l5<-l7, l1<-l3)
    perm_ph(s,
        [&](int l) {
            return (((l >> 11) & 1) << 10) | (((l >> 9) & 1) << 8) |
                   (((l >> 7) & 1) << 5) | (((l >> 3) & 1) << 1);
        },
        [&](int l) { return g_t1[256 + p4_idx8(l)]; });

    // layer2 d0: w0->l11(U48), w4->l9(U49), w8->l7(U50), w12->l3(U51)
    sweep2s<11, 9, false>(s, 48, 49); __syncthreads();
    sweep2s<7, 3, true>(s, 50, 51);   __syncthreads();
    // layer2 d1 with ring d0 folded
    sweep2sp<11, 9, false>(s, 52, 53,
        [&](int l) { return g_t2[p4_idx4(l)]; });
    __syncthreads();
    sweep2s<7, 3, true>(s, 54, 55); __syncthreads();
    // ring d1 + layer2 pool (l9<-l11, l3<-l7)
    perm_ph(s,
        [&](int l) {
            return (((l >> 11) & 1) << 9) | (((l >> 7) & 1) << 3);
        },
        [&](int l) { return g_t2[16 + p4_idx4(l)]; });

    // layer3 d0: w0->l11(U56), w8->l7(U57)
    sweep2s<11, 7, false>(s, 56, 57); __syncthreads();
    // layer3 d1 sweep (U58 on l11, U59 on l7) with t3-d0 phase folded,
    // fused with Z-measurement on l11. t3-d1 + pool3 provably no-op for <Z>.
    float acc = 0.f;
    sweep2<11, 7, false>(58, 59,
        [&](int l) { return cmul(s[SWZ(l)], g_t3[p4_idx2(l)]); },
        [&](int l, float2 v) {
            float p = fmaf(v.x, v.x, v.y * v.y);
            acc += ((l >> 11) & 1) ? -p : p;
        });

    #pragma unroll
    for (int o = 16; o > 0; o >>= 1) acc += __shfl_xor_sync(0xFFFFFFFFu, acc, o);
    if ((tid & 31) == 0) ws[tid >> 5] = acc;
    __syncthreads();
    if (tid == 0) {
        float t = 0.f;
        #pragma unroll
        for (int k = 0; k < 16; k++) t += ws[k];
        atomicAdd(&out[b], t);
    }
}

// ---------------------------------------------------------------------------
extern "C" void kernel_launch(void* const* d_in, const int* in_sizes, int n_in,
                              void* d_out, int out_size) {
    const float* xre = (const float*)d_in[0];
    const float* xim = (const float*)d_in[1];
    const float* p0  = (const float*)d_in[2];
    const float* p1  = (const float*)d_in[3];
    const float* p2  = (const float*)d_in[4];
    const float* p3  = (const float*)d_in[5];
    float* out = (float*)d_out;

    prep_kernel<<<8, 512>>>(p0, p1, p2, p3, out);
    pass1_kernel<<<256, NTP>>>(xre, xim);
    pass2_kernel<<<256, NTP>>>();
    pass3_kernel<<<256, NTP>>>();
    pass4_kernel<<<256, NTP>>>(out);
}